// round 9
// baseline (speedup 1.0000x reference)
#include <cuda_runtime.h>

// ---------------------------------------------------------------------------
// QNNClassifier, two kernels overlapped via Programmatic Dependent Launch.
//
//   ev = (1, cos x0, sin x0)^T K (1, cos x1, sin x1)
//
// prep (1 block, 16 active lanes, ~0.5us): builds the 9 batch-shared
// coefficients K into a __device__ global. Lane L=4i+j pushes basis columns
// e_i, e_j through the 2-layer circuit with factored 2x2 complex ops
// (no shuffles in the dependency chain).
//
// main (2048 blocks, 4 samples/thread — the proven 6.85us shape): launched
// with programmaticStreamSerializationAllowed=1, so it starts while prep is
// in flight; it front-batches its DRAM loads, then gridDependencySynchronize
// before reading K. Prep latency hides under the load ramp.
// ---------------------------------------------------------------------------

__device__ float g_K[9];

struct Cx { float re, im; };
__device__ __forceinline__ Cx cmadd2(Cx a, Cx x, Cx b, Cx y) {
    // a*x + b*y
    return { a.re * x.re - a.im * x.im + b.re * y.re - b.im * y.im,
             a.re * x.im + a.im * x.re + b.re * y.im + b.im * y.re };
}

__global__ void qnn_prep_kernel(const float* __restrict__ qp,
                                const float* __restrict__ fc_w,
                                const float* __restrict__ fc_b) {
    __shared__ float sA[16];
    int L = threadIdx.x;
    if (L < 16) {
        int i = L >> 2, j = L & 3;

        Cx vI[4], vJ[4];
        #pragma unroll
        for (int k = 0; k < 4; k++) {
            vI[k] = { (k == i) ? 1.f : 0.f, 0.f };
            vJ[k] = { (k == j) ? 1.f : 0.f, 0.f };
        }

        #pragma unroll
        for (int l = 0; l < 2; l++) {
            float ph0 = qp[l * 6 + 0], th0 = qp[l * 6 + 1], om0 = qp[l * 6 + 2];
            float ph1 = qp[l * 6 + 3], th1 = qp[l * 6 + 4], om1 = qp[l * 6 + 5];

            float s0, c0; __sincosf(0.5f * th0, &s0, &c0);
            float sp0, cp0, sm0, cm0;
            __sincosf(-0.5f * (ph0 + om0), &sp0, &cp0);   // ep0
            __sincosf( 0.5f * (ph0 - om0), &sm0, &cm0);   // em0
            Cx r0_00 = {  cp0 * c0,  sp0 * c0 };
            Cx r0_01 = { -cm0 * s0, -sm0 * s0 };
            Cx r0_10 = {  cm0 * s0, -sm0 * s0 };
            Cx r0_11 = {  cp0 * c0, -sp0 * c0 };

            float s1, c1; __sincosf(0.5f * th1, &s1, &c1);
            float sp1, cp1, sm1, cm1;
            __sincosf(-0.5f * (ph1 + om1), &sp1, &cp1);
            __sincosf( 0.5f * (ph1 - om1), &sm1, &cm1);
            Cx r1_00 = {  cp1 * c1,  sp1 * c1 };
            Cx r1_01 = { -cm1 * s1, -sm1 * s1 };
            Cx r1_10 = {  cm1 * s1, -sm1 * s1 };
            Cx r1_11 = {  cp1 * c1, -sp1 * c1 };

            #pragma unroll
            for (int col = 0; col < 2; col++) {
                Cx* v = col ? vJ : vI;
                Cx u0 = cmadd2(r1_00, v[0], r1_01, v[1]);
                Cx u1 = cmadd2(r1_10, v[0], r1_11, v[1]);
                Cx u2 = cmadd2(r1_00, v[2], r1_01, v[3]);
                Cx u3 = cmadd2(r1_10, v[2], r1_11, v[3]);
                Cx w0 = cmadd2(r0_00, u0, r0_01, u2);
                Cx w1 = cmadd2(r0_00, u1, r0_01, u3);
                Cx w2 = cmadd2(r0_10, u0, r0_11, u2);
                Cx w3 = cmadd2(r0_10, u1, r0_11, u3);
                // CNOT01 then CNOT10: new[r] = w[perm[r]], perm = {0,2,3,1}
                v[0] = w0; v[1] = w2; v[2] = w3; v[3] = w1;
            }
        }

        // A[i][j] = Re( sum_k z_k conj(colI[k]) colJ[k] ), z = (1,1,-1,-1)
        sA[L] = (vI[0].re * vJ[0].re + vI[0].im * vJ[0].im)
              + (vI[1].re * vJ[1].re + vI[1].im * vJ[1].im)
              - (vI[2].re * vJ[2].re + vI[2].im * vJ[2].im)
              - (vI[3].re * vJ[3].re + vI[3].im * vJ[3].im);
    }
    __syncthreads();

    if (L == 0) {
        float w = fc_w[0];
        float A00 = w * sA[0],  A01 = w * sA[1],  A02 = w * sA[2],  A03 = w * sA[3];
        float A11 = w * sA[5],  A12 = w * sA[6],  A13 = w * sA[7];
        float A22 = w * sA[10], A23 = w * sA[11], A33 = w * sA[15];
        g_K[0] = 0.25f * (A00 + A11 + A22 + A33) + fc_b[0];
        g_K[1] = 0.25f * (A00 - A11 + A22 - A33);   // C1
        g_K[2] = 0.50f * (A01 + A23);               // S1
        g_K[3] = 0.25f * (A00 + A11 - A22 - A33);   // C0
        g_K[4] = 0.25f * (A00 - A11 - A22 + A33);   // C0C1
        g_K[5] = 0.50f * (A01 - A23);               // C0S1
        g_K[6] = 0.50f * (A02 + A13);               // S0
        g_K[7] = 0.50f * (A02 - A13);               // S0C1
        g_K[8] = 0.50f * (A03 + A12);               // S0S1
    }
}

// 4 samples per thread: 2 input float4, 1 output float4.
__global__ void __launch_bounds__(256)
qnn_main_kernel(const float4* __restrict__ x4, float4* __restrict__ out4,
                int nquad) {
    unsigned t = blockIdx.x * 256u + threadIdx.x;
    if (t >= (unsigned)nquad) {
        cudaGridDependencySynchronize();
        return;
    }

    // Front-batch DRAM loads while the prep kernel finishes.
    float4 xa = __ldcs(&x4[2u * t + 0]);
    float4 xb = __ldcs(&x4[2u * t + 1]);

    cudaGridDependencySynchronize();   // prep's g_K writes now visible

    float k00 = g_K[0], k01 = g_K[1], k02 = g_K[2];
    float k10 = g_K[3], k11 = g_K[4], k12 = g_K[5];
    float k20 = g_K[6], k21 = g_K[7], k22 = g_K[8];

    float xs[8] = { xa.x, xa.y, xa.z, xa.w, xb.x, xb.y, xb.z, xb.w };

    float res[4];
    #pragma unroll
    for (int s = 0; s < 4; s++) {
        float C0, S0, C1, S1;
        __sincosf(xs[2 * s + 0], &S0, &C0);
        __sincosf(xs[2 * s + 1], &S1, &C1);
        float row0 = k00 + k01 * C1 + k02 * S1;
        float row1 = k10 + k11 * C1 + k12 * S1;
        float row2 = k20 + k21 * C1 + k22 * S1;
        res[s] = row0 + C0 * row1 + S0 * row2;
    }

    __stcs(&out4[t], make_float4(res[0], res[1], res[2], res[3]));
}

extern "C" void kernel_launch(void* const* d_in, const int* in_sizes, int n_in,
                              void* d_out, int out_size) {
    const float* x    = (const float*)d_in[0];   // [B, 2]
    const float* qp   = (const float*)d_in[1];   // [2, 2, 3]
    const float* fc_w = (const float*)d_in[2];   // [1, 1]
    const float* fc_b = (const float*)d_in[3];   // [1]

    qnn_prep_kernel<<<1, 32>>>(qp, fc_w, fc_b);

    int nquad = out_size / 4;                    // 4 samples per thread
    int threads = 256;
    int blocks = (nquad + threads - 1) / threads;   // 2048 for B=2M

    // Launch main with Programmatic Dependent Launch so it overlaps prep.
    cudaLaunchConfig_t cfg = {};
    cfg.gridDim  = dim3((unsigned)blocks, 1, 1);
    cfg.blockDim = dim3((unsigned)threads, 1, 1);
    cfg.dynamicSmemBytes = 0;
    cfg.stream = 0;
    cudaLaunchAttribute attrs[1];
    attrs[0].id = cudaLaunchAttributeProgrammaticStreamSerialization;
    attrs[0].val.programmaticStreamSerializationAllowed = 1;
    cfg.attrs = attrs;
    cfg.numAttrs = 1;

    cudaLaunchKernelEx(&cfg, qnn_main_kernel,
                       (const float4*)x, (float4*)d_out, nquad);
    (void)n_in; (void)in_sizes;
}

// round 10
// speedup vs baseline: 1.0294x; 1.0294x over previous
#include <cuda_runtime.h>

// ---------------------------------------------------------------------------
// QNNClassifier, two kernels overlapped via Programmatic Dependent Launch
// with an EXPLICIT early launch-completion trigger in the prep kernel.
//
//   ev = (1, cos x0, sin x0)^T K (1, cos x1, sin x1)
//
// prep (1 block, 16 active lanes): triggers programmatic launch completion
// IMMEDIATELY (so the main grid starts concurrently), then builds the 9
// batch-shared coefficients K into g_K. Lane L=4i+j pushes basis columns
// e_i, e_j through the 2-layer circuit with factored 2x2 complex ops.
//
// main (1024 blocks, 8 samples/thread as two strided tiles): front-batches
// all 4 float4 loads (MLP=4), then cudaGridDependencySynchronize() before
// reading g_K. Prep latency hides under the load ramp.
// ---------------------------------------------------------------------------

__device__ float g_K[9];

struct Cx { float re, im; };
__device__ __forceinline__ Cx cmadd2(Cx a, Cx x, Cx b, Cx y) {
    // a*x + b*y
    return { a.re * x.re - a.im * x.im + b.re * y.re - b.im * y.im,
             a.re * x.im + a.im * x.re + b.re * y.im + b.im * y.re };
}

__global__ void qnn_prep_kernel(const float* __restrict__ qp,
                                const float* __restrict__ fc_w,
                                const float* __restrict__ fc_b) {
    // Let the dependent (main) grid launch NOW; it will wait on
    // cudaGridDependencySynchronize() for our g_K writes.
    cudaTriggerProgrammaticLaunchCompletion();

    __shared__ float sA[16];
    int L = threadIdx.x;
    if (L < 16) {
        int i = L >> 2, j = L & 3;

        Cx vI[4], vJ[4];
        #pragma unroll
        for (int k = 0; k < 4; k++) {
            vI[k] = { (k == i) ? 1.f : 0.f, 0.f };
            vJ[k] = { (k == j) ? 1.f : 0.f, 0.f };
        }

        #pragma unroll
        for (int l = 0; l < 2; l++) {
            float ph0 = qp[l * 6 + 0], th0 = qp[l * 6 + 1], om0 = qp[l * 6 + 2];
            float ph1 = qp[l * 6 + 3], th1 = qp[l * 6 + 4], om1 = qp[l * 6 + 5];

            float s0, c0; __sincosf(0.5f * th0, &s0, &c0);
            float sp0, cp0, sm0, cm0;
            __sincosf(-0.5f * (ph0 + om0), &sp0, &cp0);   // ep0
            __sincosf( 0.5f * (ph0 - om0), &sm0, &cm0);   // em0
            Cx r0_00 = {  cp0 * c0,  sp0 * c0 };
            Cx r0_01 = { -cm0 * s0, -sm0 * s0 };
            Cx r0_10 = {  cm0 * s0, -sm0 * s0 };
            Cx r0_11 = {  cp0 * c0, -sp0 * c0 };

            float s1, c1; __sincosf(0.5f * th1, &s1, &c1);
            float sp1, cp1, sm1, cm1;
            __sincosf(-0.5f * (ph1 + om1), &sp1, &cp1);
            __sincosf( 0.5f * (ph1 - om1), &sm1, &cm1);
            Cx r1_00 = {  cp1 * c1,  sp1 * c1 };
            Cx r1_01 = { -cm1 * s1, -sm1 * s1 };
            Cx r1_10 = {  cm1 * s1, -sm1 * s1 };
            Cx r1_11 = {  cp1 * c1, -sp1 * c1 };

            #pragma unroll
            for (int col = 0; col < 2; col++) {
                Cx* v = col ? vJ : vI;
                Cx u0 = cmadd2(r1_00, v[0], r1_01, v[1]);
                Cx u1 = cmadd2(r1_10, v[0], r1_11, v[1]);
                Cx u2 = cmadd2(r1_00, v[2], r1_01, v[3]);
                Cx u3 = cmadd2(r1_10, v[2], r1_11, v[3]);
                Cx w0 = cmadd2(r0_00, u0, r0_01, u2);
                Cx w1 = cmadd2(r0_00, u1, r0_01, u3);
                Cx w2 = cmadd2(r0_10, u0, r0_11, u2);
                Cx w3 = cmadd2(r0_10, u1, r0_11, u3);
                // CNOT01 then CNOT10: new[r] = w[perm[r]], perm = {0,2,3,1}
                v[0] = w0; v[1] = w2; v[2] = w3; v[3] = w1;
            }
        }

        // A[i][j] = Re( sum_k z_k conj(colI[k]) colJ[k] ), z = (1,1,-1,-1)
        sA[L] = (vI[0].re * vJ[0].re + vI[0].im * vJ[0].im)
              + (vI[1].re * vJ[1].re + vI[1].im * vJ[1].im)
              - (vI[2].re * vJ[2].re + vI[2].im * vJ[2].im)
              - (vI[3].re * vJ[3].re + vI[3].im * vJ[3].im);
    }
    __syncthreads();

    if (L == 0) {
        float w = fc_w[0];
        float A00 = w * sA[0],  A01 = w * sA[1],  A02 = w * sA[2],  A03 = w * sA[3];
        float A11 = w * sA[5],  A12 = w * sA[6],  A13 = w * sA[7];
        float A22 = w * sA[10], A23 = w * sA[11], A33 = w * sA[15];
        g_K[0] = 0.25f * (A00 + A11 + A22 + A33) + fc_b[0];
        g_K[1] = 0.25f * (A00 - A11 + A22 - A33);   // C1
        g_K[2] = 0.50f * (A01 + A23);               // S1
        g_K[3] = 0.25f * (A00 + A11 - A22 - A33);   // C0
        g_K[4] = 0.25f * (A00 - A11 - A22 + A33);   // C0C1
        g_K[5] = 0.50f * (A01 - A23);               // C0S1
        g_K[6] = 0.50f * (A02 + A13);               // S0
        g_K[7] = 0.50f * (A02 - A13);               // S0C1
        g_K[8] = 0.50f * (A03 + A12);               // S0S1
    }
}

__device__ __forceinline__ float4 eval_tile(const float k[9],
                                            const float4& xa, const float4& xb) {
    float xs[8] = { xa.x, xa.y, xa.z, xa.w, xb.x, xb.y, xb.z, xb.w };
    float res[4];
    #pragma unroll
    for (int s = 0; s < 4; s++) {
        float C0, S0, C1, S1;
        __sincosf(xs[2 * s + 0], &S0, &C0);
        __sincosf(xs[2 * s + 1], &S1, &C1);
        float row0 = k[0] + k[1] * C1 + k[2] * S1;
        float row1 = k[3] + k[4] * C1 + k[5] * S1;
        float row2 = k[6] + k[7] * C1 + k[8] * S1;
        res[s] = row0 + C0 * row1 + S0 * row2;
    }
    return make_float4(res[0], res[1], res[2], res[3]);
}

// 8 samples per thread: two strided tiles of (2 input float4 -> 1 out float4).
__global__ void __launch_bounds__(256)
qnn_main_kernel(const float4* __restrict__ x4, float4* __restrict__ out4,
                int half_quads) {
    unsigned t = blockIdx.x * 256u + threadIdx.x;
    bool ok = t < (unsigned)half_quads;
    unsigned t2 = t + (unsigned)half_quads;

    // Front-batch ALL DRAM loads (MLP=4) while prep finishes.
    float4 xa0, xb0, xa1, xb1;
    if (ok) {
        xa0 = __ldcs(&x4[2u * t  + 0]);
        xb0 = __ldcs(&x4[2u * t  + 1]);
        xa1 = __ldcs(&x4[2u * t2 + 0]);
        xb1 = __ldcs(&x4[2u * t2 + 1]);
    }

    cudaGridDependencySynchronize();   // prep's g_K writes now visible
    if (!ok) return;

    float k[9];
    #pragma unroll
    for (int m = 0; m < 9; m++) k[m] = g_K[m];

    __stcs(&out4[t],  eval_tile(k, xa0, xb0));
    __stcs(&out4[t2], eval_tile(k, xa1, xb1));
}

extern "C" void kernel_launch(void* const* d_in, const int* in_sizes, int n_in,
                              void* d_out, int out_size) {
    const float* x    = (const float*)d_in[0];   // [B, 2]
    const float* qp   = (const float*)d_in[1];   // [2, 2, 3]
    const float* fc_w = (const float*)d_in[2];   // [1, 1]
    const float* fc_b = (const float*)d_in[3];   // [1]

    qnn_prep_kernel<<<1, 32>>>(qp, fc_w, fc_b);

    int nquad = out_size / 4;        // float4 outputs
    int half  = nquad / 2;           // two tiles per thread
    int threads = 256;
    int blocks = (half + threads - 1) / threads;   // 1024 for B=2M

    // Launch main with PDL so it overlaps prep (prep triggers early).
    cudaLaunchConfig_t cfg = {};
    cfg.gridDim  = dim3((unsigned)blocks, 1, 1);
    cfg.blockDim = dim3((unsigned)threads, 1, 1);
    cfg.dynamicSmemBytes = 0;
    cfg.stream = 0;
    cudaLaunchAttribute attrs[1];
    attrs[0].id = cudaLaunchAttributeProgrammaticStreamSerialization;
    attrs[0].val.programmaticStreamSerializationAllowed = 1;
    cfg.attrs = attrs;
    cfg.numAttrs = 1;

    cudaLaunchKernelEx(&cfg, qnn_main_kernel,
                       (const float4*)x, (float4*)d_out, half);
    (void)n_in; (void)in_sizes;
}